// round 1
// baseline (speedup 1.0000x reference)
#include <cuda_runtime.h>

// Problem constants
#define TSEQ   2048
#define NB     2
#define BT     4096      // NB*TSEQ
#define DM     1024
#define D3     3072
#define NH     16
#define HD     64        // head dim

// Scratch (device globals: no allocation allowed in kernel_launch)
__device__ float g_kqv[(size_t)BT * D3];   // [B*T, 3d]  cols: [0,1024)=K, [1024,2048)=Q, [2048,3072)=V
__device__ float g_att[(size_t)BT * DM];   // attention output [B*T, d]

// ----------------------------------------------------------------------------
// GEMM with bias: C[M,N] = A[M,K] @ B[K,N] + bias[N]
// BM=128, BN=128, BK=16, 256 threads, 8x8 per thread. M,N,K multiples of tile.
// ----------------------------------------------------------------------------
__global__ __launch_bounds__(256) void gemm_bias_kernel(
    const float* __restrict__ A, const float* __restrict__ B,
    const float* __restrict__ bias, float* __restrict__ C,
    int M, int N, int K)
{
    const int BM = 128, BN = 128, BK = 16;
    __shared__ float As[16][128];   // [k][m] (transposed)
    __shared__ float Bs[16][128];   // [k][n]

    const int tid  = threadIdx.x;
    const int m0   = blockIdx.y * BM;
    const int n0   = blockIdx.x * BN;
    const int trow = tid >> 4;      // 0..15
    const int tcol = tid & 15;      // 0..15

    // A-tile load mapping: 128 rows x 16 k -> 512 float4; 2 per thread
    const int a_row = tid >> 2;          // 0..63
    const int a_k4  = (tid & 3) * 4;     // 0,4,8,12
    // B-tile load mapping: 16 rows x 128 n -> 512 float4; 2 per thread
    const int b_row = tid >> 5;          // 0..7
    const int b_c4  = (tid & 31) * 4;    // 0..124

    float acc[8][8];
    #pragma unroll
    for (int i = 0; i < 8; i++)
        #pragma unroll
        for (int j = 0; j < 8; j++) acc[i][j] = 0.0f;

    for (int k0 = 0; k0 < K; k0 += BK) {
        #pragma unroll
        for (int it = 0; it < 2; it++) {
            const int r = a_row + it * 64;
            const float4 v = *reinterpret_cast<const float4*>(
                &A[(size_t)(m0 + r) * K + k0 + a_k4]);
            As[a_k4 + 0][r] = v.x;
            As[a_k4 + 1][r] = v.y;
            As[a_k4 + 2][r] = v.z;
            As[a_k4 + 3][r] = v.w;
        }
        #pragma unroll
        for (int it = 0; it < 2; it++) {
            const int r = b_row + it * 8;
            const float4 v = *reinterpret_cast<const float4*>(
                &B[(size_t)(k0 + r) * N + n0 + b_c4]);
            *reinterpret_cast<float4*>(&Bs[r][b_c4]) = v;
        }
        __syncthreads();

        #pragma unroll
        for (int k = 0; k < BK; k++) {
            float ar[8], br[8];
            *reinterpret_cast<float4*>(&ar[0]) =
                *reinterpret_cast<const float4*>(&As[k][trow * 8 + 0]);
            *reinterpret_cast<float4*>(&ar[4]) =
                *reinterpret_cast<const float4*>(&As[k][trow * 8 + 4]);
            *reinterpret_cast<float4*>(&br[0]) =
                *reinterpret_cast<const float4*>(&Bs[k][tcol * 8 + 0]);
            *reinterpret_cast<float4*>(&br[4]) =
                *reinterpret_cast<const float4*>(&Bs[k][tcol * 8 + 4]);
            #pragma unroll
            for (int i = 0; i < 8; i++)
                #pragma unroll
                for (int j = 0; j < 8; j++)
                    acc[i][j] += ar[i] * br[j];
        }
        __syncthreads();
    }

    #pragma unroll
    for (int i = 0; i < 8; i++) {
        const int m = m0 + trow * 8 + i;
        #pragma unroll
        for (int j4 = 0; j4 < 8; j4 += 4) {
            const int n = n0 + tcol * 8 + j4;
            const float4 bv = *reinterpret_cast<const float4*>(&bias[n]);
            float4 o;
            o.x = acc[i][j4 + 0] + bv.x;
            o.y = acc[i][j4 + 1] + bv.y;
            o.z = acc[i][j4 + 2] + bv.z;
            o.w = acc[i][j4 + 3] + bv.w;
            *reinterpret_cast<float4*>(&C[(size_t)m * N + n]) = o;
        }
    }
}

// ----------------------------------------------------------------------------
// Flash attention (causal, fp32). One CTA = (q-block of 64 rows, head, batch).
// KV tiles of 32. 256 threads: 16x16 grid, each thread 4 rows x (2 S-cols / 4 O-cols).
// ----------------------------------------------------------------------------
#define BR 64
#define BC 32

__global__ __launch_bounds__(256) void attn_kernel()
{
    const int qb = blockIdx.x;      // 0..31
    const int h  = blockIdx.y;      // 0..15
    const int b  = blockIdx.z;      // 0..1
    const int q0 = qb * BR;

    __shared__ float Qt[HD][BR + 4];   // [c][i], stride 68 (float4-aligned)
    __shared__ float Kt[HD][BC + 1];   // [c][j], stride 33
    __shared__ float Vs[BC][HD];       // [j][c], stride 64
    __shared__ float Ss[BR][BC + 1];   // [i][j], stride 33
    __shared__ float mrow[BR], lrow[BR], arow[BR];

    const int tid  = threadIdx.x;
    const int trow = tid >> 4;       // 0..15 -> rows trow*4..+3
    const int tcol = tid & 15;       // 0..15 -> S cols tcol*2..+1 / O cols tcol*4..+3

    // Load Q tile (transposed into smem). Q = cols [DM, 2*DM) of kqv.
    {
        const int r0 = tid >> 4;               // 0..15
        const int c4 = (tid & 15) * 4;
        #pragma unroll
        for (int it = 0; it < 4; it++) {
            const int i = r0 + it * 16;
            const float4 v = *reinterpret_cast<const float4*>(
                &g_kqv[(size_t)(b * TSEQ + q0 + i) * D3 + DM + h * HD + c4]);
            Qt[c4 + 0][i] = v.x;
            Qt[c4 + 1][i] = v.y;
            Qt[c4 + 2][i] = v.z;
            Qt[c4 + 3][i] = v.w;
        }
    }
    if (tid < BR) { mrow[tid] = -1e30f; lrow[tid] = 0.0f; }

    float acc[4][4];
    #pragma unroll
    for (int i = 0; i < 4; i++)
        #pragma unroll
        for (int j = 0; j < 4; j++) acc[i][j] = 0.0f;

    const int ntiles = (q0 + BR) / BC;    // 2*(qb+1)
    for (int tile = 0; tile < ntiles; tile++) {
        const int s0 = tile * BC;
        __syncthreads();
        // Load K (transposed) and V tiles. K = cols [0,DM), V = cols [2*DM,3*DM).
        {
            const int jr = tid >> 4;           // 0..15
            const int c4 = (tid & 15) * 4;
            #pragma unroll
            for (int it = 0; it < 2; it++) {
                const int j = jr + it * 16;
                const size_t row = (size_t)(b * TSEQ + s0 + j);
                const float4 kv = *reinterpret_cast<const float4*>(
                    &g_kqv[row * D3 + h * HD + c4]);
                Kt[c4 + 0][j] = kv.x;
                Kt[c4 + 1][j] = kv.y;
                Kt[c4 + 2][j] = kv.z;
                Kt[c4 + 3][j] = kv.w;
                const float4 vv = *reinterpret_cast<const float4*>(
                    &g_kqv[row * D3 + 2 * DM + h * HD + c4]);
                *reinterpret_cast<float4*>(&Vs[j][c4]) = vv;
            }
        }
        __syncthreads();

        // S = scale * Q @ K^T, causal mask. Each thread: 4 rows x 2 cols.
        {
            float sacc[4][2];
            #pragma unroll
            for (int i = 0; i < 4; i++) { sacc[i][0] = 0.f; sacc[i][1] = 0.f; }
            #pragma unroll 8
            for (int c = 0; c < HD; c++) {
                const float4 q4 = *reinterpret_cast<const float4*>(&Qt[c][trow * 4]);
                const float k0 = Kt[c][tcol * 2 + 0];
                const float k1 = Kt[c][tcol * 2 + 1];
                sacc[0][0] += q4.x * k0; sacc[0][1] += q4.x * k1;
                sacc[1][0] += q4.y * k0; sacc[1][1] += q4.y * k1;
                sacc[2][0] += q4.z * k0; sacc[2][1] += q4.z * k1;
                sacc[3][0] += q4.w * k0; sacc[3][1] += q4.w * k1;
            }
            #pragma unroll
            for (int ii = 0; ii < 4; ii++) {
                const int gi = q0 + trow * 4 + ii;
                #pragma unroll
                for (int jj = 0; jj < 2; jj++) {
                    const int gj = s0 + tcol * 2 + jj;
                    float v = sacc[ii][jj] * 0.125f;   // 1/sqrt(64)
                    if (gj > gi) v = -1e30f;
                    Ss[trow * 4 + ii][tcol * 2 + jj] = v;
                }
            }
        }
        __syncthreads();

        // Online softmax: row = tid/4, 4 lanes per row, 8 cols each.
        {
            const int srow = tid >> 2;
            const int sq   = tid & 3;
            float mloc = -1e30f;
            #pragma unroll
            for (int jj = 0; jj < 8; jj++)
                mloc = fmaxf(mloc, Ss[srow][sq * 8 + jj]);
            mloc = fmaxf(mloc, __shfl_xor_sync(0xFFFFFFFFu, mloc, 1));
            mloc = fmaxf(mloc, __shfl_xor_sync(0xFFFFFFFFu, mloc, 2));
            const float mold = mrow[srow];
            const float mnew = fmaxf(mold, mloc);
            float ssum = 0.0f;
            #pragma unroll
            for (int jj = 0; jj < 8; jj++) {
                const float p = __expf(Ss[srow][sq * 8 + jj] - mnew);
                Ss[srow][sq * 8 + jj] = p;
                ssum += p;
            }
            ssum += __shfl_xor_sync(0xFFFFFFFFu, ssum, 1);
            ssum += __shfl_xor_sync(0xFFFFFFFFu, ssum, 2);
            if (sq == 0) {
                const float alpha = __expf(mold - mnew);
                arow[srow] = alpha;
                lrow[srow] = lrow[srow] * alpha + ssum;
                mrow[srow] = mnew;
            }
        }
        __syncthreads();

        // O = O*alpha + P @ V. Each thread: 4 rows x 4 cols.
        {
            #pragma unroll
            for (int ii = 0; ii < 4; ii++) {
                const float a = arow[trow * 4 + ii];
                acc[ii][0] *= a; acc[ii][1] *= a; acc[ii][2] *= a; acc[ii][3] *= a;
            }
            #pragma unroll 4
            for (int j = 0; j < BC; j++) {
                const float4 v4 = *reinterpret_cast<const float4*>(&Vs[j][tcol * 4]);
                #pragma unroll
                for (int ii = 0; ii < 4; ii++) {
                    const float p = Ss[trow * 4 + ii][j];
                    acc[ii][0] += p * v4.x;
                    acc[ii][1] += p * v4.y;
                    acc[ii][2] += p * v4.z;
                    acc[ii][3] += p * v4.w;
                }
            }
        }
    }
    __syncthreads();

    // Normalize and write to g_att[b*T + t][h*64 + c]
    #pragma unroll
    for (int ii = 0; ii < 4; ii++) {
        const int i   = trow * 4 + ii;
        const float n = 1.0f / lrow[i];
        float4 o;
        o.x = acc[ii][0] * n;
        o.y = acc[ii][1] * n;
        o.z = acc[ii][2] * n;
        o.w = acc[ii][3] * n;
        *reinterpret_cast<float4*>(
            &g_att[(size_t)(b * TSEQ + q0 + i) * DM + h * HD + tcol * 4]) = o;
    }
}

// ----------------------------------------------------------------------------
extern "C" void kernel_launch(void* const* d_in, const int* in_sizes, int n_in,
                              void* d_out, int out_size)
{
    (void)in_sizes; (void)n_in; (void)out_size;
    const float* x     = (const float*)d_in[0];
    const float* W_kqv = (const float*)d_in[1];
    const float* b_kqv = (const float*)d_in[2];
    const float* W_o   = (const float*)d_in[3];
    const float* b_o   = (const float*)d_in[4];
    float* out = (float*)d_out;

    float *kqv_ptr, *att_ptr;
    cudaGetSymbolAddress((void**)&kqv_ptr, g_kqv);
    cudaGetSymbolAddress((void**)&att_ptr, g_att);

    // 1) KQV projection: [4096,1024] @ [1024,3072] + b
    gemm_bias_kernel<<<dim3(D3 / 128, BT / 128), 256>>>(
        x, W_kqv, b_kqv, kqv_ptr, BT, D3, DM);
    // 2) Causal flash attention per (q-block, head, batch)
    attn_kernel<<<dim3(TSEQ / BR, NH, NB), 256>>>();
    // 3) Output projection: [4096,1024] @ [1024,1024] + b
    gemm_bias_kernel<<<dim3(DM / 128, BT / 128), 256>>>(
        att_ptr, W_o, b_o, out, BT, DM, DM);
}

// round 4
// speedup vs baseline: 3.5300x; 3.5300x over previous
#include <cuda_runtime.h>
#include <cstdint>

// Problem constants
#define TSEQ   2048
#define NB     2
#define BT     4096      // NB*TSEQ
#define DM     1024
#define D3     3072
#define NH     16
#define HD     64        // head dim

// Scratch (device globals: no allocation allowed in kernel_launch)
__device__ float g_kqv[(size_t)BT * D3];   // [B*T, 3d]  cols: [0,1024)=K, [1024,2048)=Q, [2048,3072)=V (tf32)
__device__ float g_att[(size_t)BT * DM];   // attention output [B*T, d] (tf32)
__device__ float g_xa [(size_t)BT * DM];   // x, tf32-rounded
__device__ float g_wk [(size_t)DM * D3];   // W_kqv, tf32-rounded ([K=1024, N=3072])
__device__ float g_wo [(size_t)DM * DM];   // W_o,   tf32-rounded

// ============================================================================
// helpers
// ============================================================================
__device__ __forceinline__ uint32_t smem_u32(const void* p) {
    uint32_t a;
    asm("{ .reg .u64 t; cvta.to.shared.u64 t, %1; cvt.u32.u64 %0, t; }" : "=r"(a) : "l"(p));
    return a;
}
__device__ __forceinline__ float tf32_rna(float x) {
    uint32_t u;
    asm("cvt.rna.tf32.f32 %0, %1;" : "=r"(u) : "f"(x));
    return __uint_as_float(u);
}

// m16n8k8 tf32 mma: D = A(16x8, row) * B(8x8, col) + D
#define MMA_TF32(c, a0, a1, a2, a3, b0, b1)                                   \
    asm volatile("mma.sync.aligned.m16n8k8.row.col.f32.tf32.tf32.f32 "        \
        "{%0,%1,%2,%3}, {%4,%5,%6,%7}, {%8,%9}, {%0,%1,%2,%3};"               \
        : "+f"((c)[0]), "+f"((c)[1]), "+f"((c)[2]), "+f"((c)[3])              \
        : "r"(a0), "r"(a1), "r"(a2), "r"(a3), "r"(b0), "r"(b1))

#define CP_ASYNC16(dst, src) \
    asm volatile("cp.async.cg.shared.global [%0], [%1], 16;" :: "r"(dst), "l"(src))
#define CP_COMMIT()  asm volatile("cp.async.commit_group;" ::: "memory")
#define CP_WAIT0()   asm volatile("cp.async.wait_group 0;" ::: "memory")
#define CP_WAIT1()   asm volatile("cp.async.wait_group 1;" ::: "memory")

// ============================================================================
// Prep: elementwise tf32 rounding
// ============================================================================
__global__ void round_tf32_kernel(const float* __restrict__ in, float* __restrict__ out) {
    int i = blockIdx.x * blockDim.x + threadIdx.x;
    float4 v = reinterpret_cast<const float4*>(in)[i];
    v.x = tf32_rna(v.x); v.y = tf32_rna(v.y);
    v.z = tf32_rna(v.z); v.w = tf32_rna(v.w);
    reinterpret_cast<float4*>(out)[i] = v;
}

// ============================================================================
// GEMM (mma.sync tf32):  C[M,N] = A[M,K] @ W[K,N] + bias[N]
// 128x128 block, BK=32, cp.async double-buffer, 256 threads = 8 warps (2x4),
// warp tile 64x32 = 4x4 grid of m16n8k8.
// smem: As[2][128][36] + Bs[2][32][136]
// ============================================================================
#define G_SMEM_BYTES ((2 * 128 * 36 + 2 * 32 * 136) * 4)   // 71680

__global__ __launch_bounds__(256, 2) void gemm_mma_kernel(
    const float* __restrict__ A, const float* __restrict__ W,
    const float* __restrict__ bias, float* __restrict__ C,
    int M, int N, int K, int round_out)
{
    extern __shared__ float sm[];
    float* As = sm;                  // [2][128][36]
    float* Bs = sm + 2 * 128 * 36;   // [2][32][136]

    const int tid  = threadIdx.x;
    const int wid  = tid >> 5;
    const int lane = tid & 31;
    const int g    = lane >> 2;      // groupID 0..7
    const int tig  = lane & 3;       // thread-in-group 0..3
    const int m0 = blockIdx.y * 128;
    const int n0 = blockIdx.x * 128;
    const int wm = (wid >> 2) * 64;  // warp m offset (0/64)
    const int wn = (wid & 3) * 32;   // warp n offset

    float acc[4][4][4];
    #pragma unroll
    for (int mt = 0; mt < 4; mt++)
        #pragma unroll
        for (int nt = 0; nt < 4; nt++)
            #pragma unroll
            for (int e = 0; e < 4; e++) acc[mt][nt][e] = 0.0f;

    const int nchunk = K / 32;

    auto issue = [&](int ch, int s) {
        #pragma unroll
        for (int i = 0; i < 4; i++) {
            const int idx = tid + i * 256;            // 0..1023
            const int r = idx >> 3, c4 = (idx & 7) * 4;
            const uint32_t d = smem_u32(&As[s * 4608 + r * 36 + c4]);
            CP_ASYNC16(d, &A[(size_t)(m0 + r) * K + ch * 32 + c4]);
        }
        #pragma unroll
        for (int i = 0; i < 4; i++) {
            const int idx = tid + i * 256;
            const int r = idx >> 5, c4 = (idx & 31) * 4;
            const uint32_t d = smem_u32(&Bs[s * 4352 + r * 136 + c4]);
            CP_ASYNC16(d, &W[(size_t)(ch * 32 + r) * N + n0 + c4]);
        }
        CP_COMMIT();
    };

    issue(0, 0);
    for (int ch = 0; ch < nchunk; ch++) {
        const int s = ch & 1;
        if (ch + 1 < nchunk) { issue(ch + 1, s ^ 1); CP_WAIT1(); }
        else                 { CP_WAIT0(); }
        __syncthreads();

        const float* as = As + s * 4608;
        const float* bs = Bs + s * 4352;
        #pragma unroll
        for (int ks = 0; ks < 4; ks++) {
            const int k = ks * 8;
            uint32_t a[4][4];
            #pragma unroll
            for (int mt = 0; mt < 4; mt++) {
                const float* ap = as + (wm + mt * 16 + g) * 36 + k + tig;
                a[mt][0] = __float_as_uint(ap[0]);
                a[mt][1] = __float_as_uint(ap[8 * 36]);
                a[mt][2] = __float_as_uint(ap[4]);
                a[mt][3] = __float_as_uint(ap[8 * 36 + 4]);
            }
            #pragma unroll
            for (int nt = 0; nt < 4; nt++) {
                const float* bp = bs + (k + tig) * 136 + wn + nt * 8 + g;
                const uint32_t b0 = __float_as_uint(bp[0]);
                const uint32_t b1 = __float_as_uint(bp[4 * 136]);
                #pragma unroll
                for (int mt = 0; mt < 4; mt++)
                    MMA_TF32(acc[mt][nt], a[mt][0], a[mt][1], a[mt][2], a[mt][3], b0, b1);
            }
        }
        __syncthreads();
    }

    #pragma unroll
    for (int mt = 0; mt < 4; mt++) {
        const int r_lo = m0 + wm + mt * 16 + g;
        const int r_hi = r_lo + 8;
        #pragma unroll
        for (int nt = 0; nt < 4; nt++) {
            const int c = n0 + wn + nt * 8 + 2 * tig;
            const float b0 = bias[c], b1 = bias[c + 1];
            float v0 = acc[mt][nt][0] + b0;
            float v1 = acc[mt][nt][1] + b1;
            float v2 = acc[mt][nt][2] + b0;
            float v3 = acc[mt][nt][3] + b1;
            if (round_out) {
                v0 = tf32_rna(v0); v1 = tf32_rna(v1);
                v2 = tf32_rna(v2); v3 = tf32_rna(v3);
            }
            *reinterpret_cast<float2*>(&C[(size_t)r_lo * N + c]) = make_float2(v0, v1);
            *reinterpret_cast<float2*>(&C[(size_t)r_hi * N + c]) = make_float2(v2, v3);
        }
    }
}

// ============================================================================
// Flash attention, mma.sync tf32. CTA = 64 q-rows x (head, batch), 128 thr.
// 4 warps; warp owns 16 q-rows -> softmax fully in fragments + quad shuffles.
// KV tiles 64 wide. smem: Qs[64][68] Ks[64][68] Vs[64][72] Ps[64][68].
// ============================================================================
#define ASC 0.18033688011112042f     // 0.125 * log2(e)
#define PS  68                        // Ps row stride (fixed from 36: P is 64 wide)
#define A_SMEM_BYTES ((64 * 68 + 64 * 68 + 64 * 72 + 64 * PS) * 4)   // 70656

__global__ __launch_bounds__(128) void attn_mma_kernel()
{
    extern __shared__ float sm[];
    float* Qs = sm;              // [64][68]
    float* Ks = sm + 4352;       // [64][68]
    float* Vs = sm + 8704;       // [64][72]
    float* Ps = sm + 13312;      // [64][PS]

    const int tid  = threadIdx.x;
    const int wid  = tid >> 5;
    const int lane = tid & 31;
    const int g    = lane >> 2;
    const int tig  = lane & 3;
    const int qb = blockIdx.x;
    const int h  = blockIdx.y;
    const int b  = blockIdx.z;
    const int q0 = qb * 64;
    const int wr = wid * 16;                 // warp's q-row base within tile
    const int r_lo_g = q0 + wr + g;          // global q row (lo)
    const int r_hi_g = r_lo_g + 8;

    // Load Q tile once (g_kqv already tf32-rounded by GEMM1 epilogue)
    #pragma unroll
    for (int i = 0; i < 8; i++) {
        const int idx = tid + i * 128;
        const int r = idx >> 4, c4 = (idx & 15) * 4;
        *reinterpret_cast<float4*>(&Qs[r * 68 + c4]) =
            *reinterpret_cast<const float4*>(
                &g_kqv[(size_t)(b * TSEQ + q0 + r) * D3 + DM + h * HD + c4]);
    }

    float o[8][4];
    #pragma unroll
    for (int nt = 0; nt < 8; nt++)
        #pragma unroll
        for (int e = 0; e < 4; e++) o[nt][e] = 0.0f;
    float m_lo = -1e30f, m_hi = -1e30f, l_lo = 0.0f, l_hi = 0.0f;

    for (int tile = 0; tile <= qb; tile++) {
        const int s0 = tile * 64;
        __syncthreads();
        #pragma unroll
        for (int i = 0; i < 8; i++) {
            const int idx = tid + i * 128;
            const int r = idx >> 4, c4 = (idx & 15) * 4;
            const size_t gr = (size_t)(b * TSEQ + s0 + r) * D3 + h * HD + c4;
            *reinterpret_cast<float4*>(&Ks[r * 68 + c4]) =
                *reinterpret_cast<const float4*>(&g_kqv[gr]);
            *reinterpret_cast<float4*>(&Vs[r * 72 + c4]) =
                *reinterpret_cast<const float4*>(&g_kqv[gr + 2 * DM]);
        }
        __syncthreads();

        // ---- S = Q @ K^T  (64-deep), warp computes 16x64 in frags ----
        float sacc[8][4];
        #pragma unroll
        for (int nt = 0; nt < 8; nt++)
            #pragma unroll
            for (int e = 0; e < 4; e++) sacc[nt][e] = 0.0f;

        #pragma unroll
        for (int ks = 0; ks < 8; ks++) {
            const int k = ks * 8;
            const uint32_t a0 = __float_as_uint(Qs[(wr + g) * 68 + k + tig]);
            const uint32_t a1 = __float_as_uint(Qs[(wr + g + 8) * 68 + k + tig]);
            const uint32_t a2 = __float_as_uint(Qs[(wr + g) * 68 + k + tig + 4]);
            const uint32_t a3 = __float_as_uint(Qs[(wr + g + 8) * 68 + k + tig + 4]);
            #pragma unroll
            for (int nt = 0; nt < 8; nt++) {
                const uint32_t b0 = __float_as_uint(Ks[(nt * 8 + g) * 68 + k + tig]);
                const uint32_t b1 = __float_as_uint(Ks[(nt * 8 + g) * 68 + k + tig + 4]);
                MMA_TF32(sacc[nt], a0, a1, a2, a3, b0, b1);
            }
        }

        // ---- scale (into log2 domain) + causal mask (diagonal tile only) ----
        const bool masked = (tile == qb);
        #pragma unroll
        for (int nt = 0; nt < 8; nt++) {
            float v0 = sacc[nt][0] * ASC, v1 = sacc[nt][1] * ASC;
            float v2 = sacc[nt][2] * ASC, v3 = sacc[nt][3] * ASC;
            if (masked) {
                const int c0 = s0 + nt * 8 + 2 * tig, c1 = c0 + 1;
                if (c0 > r_lo_g) v0 = -1e30f;
                if (c1 > r_lo_g) v1 = -1e30f;
                if (c0 > r_hi_g) v2 = -1e30f;
                if (c1 > r_hi_g) v3 = -1e30f;
            }
            sacc[nt][0] = v0; sacc[nt][1] = v1; sacc[nt][2] = v2; sacc[nt][3] = v3;
        }

        // ---- online softmax: row max over 8 regs + quad shuffles ----
        float xl = -1e30f, xh = -1e30f;
        #pragma unroll
        for (int nt = 0; nt < 8; nt++) {
            xl = fmaxf(xl, fmaxf(sacc[nt][0], sacc[nt][1]));
            xh = fmaxf(xh, fmaxf(sacc[nt][2], sacc[nt][3]));
        }
        xl = fmaxf(xl, __shfl_xor_sync(0xFFFFFFFFu, xl, 1));
        xl = fmaxf(xl, __shfl_xor_sync(0xFFFFFFFFu, xl, 2));
        xh = fmaxf(xh, __shfl_xor_sync(0xFFFFFFFFu, xh, 1));
        xh = fmaxf(xh, __shfl_xor_sync(0xFFFFFFFFu, xh, 2));
        const float mn_lo = fmaxf(m_lo, xl);
        const float mn_hi = fmaxf(m_hi, xh);
        const float al = exp2f(m_lo - mn_lo);
        const float ah = exp2f(m_hi - mn_hi);
        m_lo = mn_lo; m_hi = mn_hi;

        float sl = 0.0f, sh = 0.0f;
        #pragma unroll
        for (int nt = 0; nt < 8; nt++) {
            const float p0 = exp2f(sacc[nt][0] - mn_lo);
            const float p1 = exp2f(sacc[nt][1] - mn_lo);
            const float p2 = exp2f(sacc[nt][2] - mn_hi);
            const float p3 = exp2f(sacc[nt][3] - mn_hi);
            sl += p0 + p1; sh += p2 + p3;
            const int c = nt * 8 + 2 * tig;
            *reinterpret_cast<float2*>(&Ps[(wr + g) * PS + c]) =
                make_float2(tf32_rna(p0), tf32_rna(p1));
            *reinterpret_cast<float2*>(&Ps[(wr + g + 8) * PS + c]) =
                make_float2(tf32_rna(p2), tf32_rna(p3));
        }
        sl += __shfl_xor_sync(0xFFFFFFFFu, sl, 1);
        sl += __shfl_xor_sync(0xFFFFFFFFu, sl, 2);
        sh += __shfl_xor_sync(0xFFFFFFFFu, sh, 1);
        sh += __shfl_xor_sync(0xFFFFFFFFu, sh, 2);
        l_lo = l_lo * al + sl;
        l_hi = l_hi * ah + sh;
        #pragma unroll
        for (int nt = 0; nt < 8; nt++) {
            o[nt][0] *= al; o[nt][1] *= al;
            o[nt][2] *= ah; o[nt][3] *= ah;
        }
        __syncwarp();

        // ---- O += P @ V  (P 16x64, V 64x64) ----
        #pragma unroll
        for (int ks = 0; ks < 8; ks++) {
            const int k = ks * 8;
            const uint32_t a0 = __float_as_uint(Ps[(wr + g) * PS + k + tig]);
            const uint32_t a1 = __float_as_uint(Ps[(wr + g + 8) * PS + k + tig]);
            const uint32_t a2 = __float_as_uint(Ps[(wr + g) * PS + k + tig + 4]);
            const uint32_t a3 = __float_as_uint(Ps[(wr + g + 8) * PS + k + tig + 4]);
            #pragma unroll
            for (int nt = 0; nt < 8; nt++) {
                const uint32_t b0 = __float_as_uint(Vs[(k + tig) * 72 + nt * 8 + g]);
                const uint32_t b1 = __float_as_uint(Vs[(k + tig + 4) * 72 + nt * 8 + g]);
                MMA_TF32(o[nt], a0, a1, a2, a3, b0, b1);
            }
        }
    }

    // epilogue: normalize, round to tf32 (GEMM2 consumes as A), store
    const float il = 1.0f / l_lo;
    const float ih = 1.0f / l_hi;
    #pragma unroll
    for (int nt = 0; nt < 8; nt++) {
        const int c = h * HD + nt * 8 + 2 * tig;
        *reinterpret_cast<float2*>(&g_att[(size_t)(b * TSEQ + r_lo_g) * DM + c]) =
            make_float2(tf32_rna(o[nt][0] * il), tf32_rna(o[nt][1] * il));
        *reinterpret_cast<float2*>(&g_att[(size_t)(b * TSEQ + r_hi_g) * DM + c]) =
            make_float2(tf32_rna(o[nt][2] * ih), tf32_rna(o[nt][3] * ih));
    }
}

// ----------------------------------------------------------------------------
extern "C" void kernel_launch(void* const* d_in, const int* in_sizes, int n_in,
                              void* d_out, int out_size)
{
    (void)in_sizes; (void)n_in; (void)out_size;
    const float* x     = (const float*)d_in[0];
    const float* W_kqv = (const float*)d_in[1];
    const float* b_kqv = (const float*)d_in[2];
    const float* W_o   = (const float*)d_in[3];
    const float* b_o   = (const float*)d_in[4];
    float* out = (float*)d_out;

    float *kqv_p, *att_p, *xa_p, *wk_p, *wo_p;
    cudaGetSymbolAddress((void**)&kqv_p, g_kqv);
    cudaGetSymbolAddress((void**)&att_p, g_att);
    cudaGetSymbolAddress((void**)&xa_p,  g_xa);
    cudaGetSymbolAddress((void**)&wk_p,  g_wk);
    cudaGetSymbolAddress((void**)&wo_p,  g_wo);

    cudaFuncSetAttribute(gemm_mma_kernel,
                         cudaFuncAttributeMaxDynamicSharedMemorySize, G_SMEM_BYTES);
    cudaFuncSetAttribute(attn_mma_kernel,
                         cudaFuncAttributeMaxDynamicSharedMemorySize, A_SMEM_BYTES);

    // prep: tf32 rounding (elementwise, no transpose needed)
    round_tf32_kernel<<<(BT * DM / 4) / 256, 256>>>(x, xa_p);
    round_tf32_kernel<<<((size_t)DM * D3 / 4) / 256, 256>>>(W_kqv, wk_p);
    round_tf32_kernel<<<((size_t)DM * DM / 4) / 256, 256>>>(W_o, wo_p);

    // 1) KQV projection (outputs rounded to tf32 for attention)
    gemm_mma_kernel<<<dim3(D3 / 128, BT / 128), 256, G_SMEM_BYTES>>>(
        xa_p, wk_p, b_kqv, kqv_p, BT, D3, DM, 1);
    // 2) Causal flash attention (mma.sync tf32)
    attn_mma_kernel<<<dim3(TSEQ / 64, NH, NB), 128, A_SMEM_BYTES>>>();
    // 3) Output projection (final fp32 output, no rounding)
    gemm_mma_kernel<<<dim3(DM / 128, BT / 128), 256, G_SMEM_BYTES>>>(
        att_p, wo_p, b_o, out, BT, DM, DM, 0);
}